// round 9
// baseline (speedup 1.0000x reference)
#include <cuda_runtime.h>

// Inverse discrete Hough transform, round 9: row-loop gather.
// Currency established from R2/R5/R8 calibration: each EXECUTED LDG.128 costs
// ~4 cyc/SM flat (RF writeback), predicated-off loads are free. So: loop over
// the <=4 distinct rho rows of each 4-px strip per angle (independent loads,
// addresses from SMEM table) and route values to pixel accumulators with
// predicated packed adds. No load-load dependences (unlike R3-R7 chains).
// Pass B: angles 0..44 & 135..179, strips along y -> pBT[x*256+y][nc]
// Pass A: angles 45..134, strips along x, += pBT fold, -> out.

#define NA 180
#define NR 400
#define NC 256
#define OH 256
#define OW 256
#define AR (NA * NR)      // 72000
#define HW (OH * OW)      // 65536
#define NS4 16384         // 65536 px / 4 per strip

typedef unsigned long long ull;

__device__ float  g_accT[AR * NC];                   // 73.7 MB: [a*400+r][nc]
__device__ float2 g_trig[NA];
__device__ unsigned g_offA[(size_t)NS4 * 90 * 4];    // [strip4][arel][px] byte offs
__device__ unsigned g_offB[(size_t)NS4 * 90 * 4];
__device__ ull    g_pBT[(size_t)HW * 128];           // pass-B partial, [x*256+y][nc/2]

__device__ __forceinline__ float u64lo(ull u) {
    float a, b; asm("mov.b64 {%0,%1}, %2;" : "=f"(a), "=f"(b) : "l"(u)); return a;
}
__device__ __forceinline__ float u64hi(ull u) {
    float a, b; asm("mov.b64 {%0,%1}, %2;" : "=f"(a), "=f"(b) : "l"(u)); return b;
}
__device__ __forceinline__ ull fadd2(ull a, ull b) {
    ull r;
    asm("add.rn.f32x2 %0, %1, %2;" : "=l"(r) : "l"(a), "l"(b));
    return r;
}

// unconditional 16B gather
#define LDG2(v0, v1, addr)                                             \
    asm("ld.global.nc.v2.u64 {%0,%1}, [%2];"                           \
        : "=l"(v0), "=l"(v1) : "l"(addr))
// gather executed only when cond != 0 (else registers keep old values;
// consumers are predicated on row-match which implies cond, so stale is fine)
#define PLDG2B(v0, v1, cond, addr)                                     \
    asm("{\n\t.reg .pred q;\n\tsetp.ne.u32 q, %2, 0;\n\t"              \
        "@q ld.global.nc.v2.u64 {%0,%1}, [%3];\n\t}"                   \
        : "+l"(v0), "+l"(v1) : "r"(cond), "l"(addr))
// pixel-row match: if (opx == off) acc[0..3] += v[0..3]   (packed f32x2, rn)
#define PADD4(a0, a1, a2, a3, v0, v1, v2, v3, opx, off)                \
    asm("{\n\t.reg .pred q;\n\tsetp.eq.u32 q, %8, %9;\n\t"             \
        "@q add.rn.f32x2 %0, %0, %4;\n\t"                              \
        "@q add.rn.f32x2 %1, %1, %5;\n\t"                              \
        "@q add.rn.f32x2 %2, %2, %6;\n\t"                              \
        "@q add.rn.f32x2 %3, %3, %7;\n\t}"                             \
        : "+l"(a0), "+l"(a1), "+l"(a2), "+l"(a3)                       \
        : "l"(v0), "l"(v1), "l"(v2), "l"(v3), "r"(opx), "r"(off))

__global__ void k_trig() {
    int a = threadIdx.x;
    if (a < NA) {
        // f32 theta (rn multiply), then correctly-rounded f32 cos/sin via
        // double (immune to fast-math; matches the JAX reference bit-exactly).
        float t = __fmul_rn((float)a, (float)(3.14159265358979323846 / 180.0));
        double td = (double)t;
        g_trig[a] = make_float2((float)cos(td), (float)sin(td));
    }
}

// 32x32 tiled transpose of acc[256][72000] -> g_accT[72000][256]
__global__ void k_transpose(const float* __restrict__ in) {
    __shared__ float tile[32][33];
    int tx = threadIdx.x, ty = threadIdx.y;           // 32 x 8
    int ar = blockIdx.x * 32 + tx;
#pragma unroll
    for (int k = 0; k < 4; k++)
        tile[ty + k * 8][tx] = in[(size_t)(blockIdx.y * 32 + ty + k * 8) * AR + ar];
    __syncthreads();
    int nc2 = blockIdx.y * 32 + tx;
#pragma unroll
    for (int k = 0; k < 4; k++)
        g_accT[(size_t)(blockIdx.x * 32 + ty + k * 8) * NC + nc2] = tile[tx][ty + k * 8];
}

// Precompute exact rho byte-offset tables: [strip4][arel][px].
__global__ void k_tab() {
    int idx = blockIdx.x * 256 + threadIdx.x;   // 180 * 65536 threads
    int p = idx & 3;
    int s = (idx >> 2) & (NS4 - 1);
    int a = idx >> 16;
    bool isA = (a >= 45 && a < 135);
    int line = s >> 6, q0 = (s & 63) << 2;
    int x = isA ? (q0 + p) : line;
    int y = isA ? line : (q0 + p);
    float2 cs = g_trig[a];
    // exact reference arithmetic: rn(rn(xc*cos) + rn(yc*sin)), round-half-even
    float sum = __fadd_rn(__fmul_rn((float)(x - OW / 2), cs.x),
                          __fmul_rn((float)(y - OH / 2), cs.y));
    unsigned off = (unsigned)(a * NR + __float2int_rn(sum) + NR / 2) << 10;
    int arel = isA ? (a - 45) : (a < 45 ? a : a - 90);
    unsigned* tab = isA ? g_offA : g_offB;
    tab[((size_t)s * 90 + arel) * 4 + p] = off;
}

// Main pass. CTA = 8 warps = 8 consecutive 4-px strips (32 px); warp covers
// its strip's 4 px x all 256 channels (lane = 16B channel slice, two halves).
// Per angle: rows lo..hi (<=4, contiguous); 2 independent LDG.128 per row;
// predicated adds route rows to pixels. Rows 2-3 in a ~29%-taken branch.
template <int PASS>
__global__ __launch_bounds__(256, 3) void k_pass(float* __restrict__ outp) {
    __shared__ union SM {
        uint4 t4[720];               // 8 strips x 90 angles x 4 offsets
        float stage[32 * 264];       // pass-A epilogue: 32 px x 256 ch (pad 8)
    } sm;

    const unsigned* tab = (PASS == 0) ? g_offA : g_offB;
    int tid = threadIdx.x;
    {
        const uint4* gsrc = (const uint4*)(tab + (size_t)blockIdx.x * 8 * 90 * 4);
        sm.t4[tid]       = __ldg(gsrc + tid);
        sm.t4[tid + 256] = __ldg(gsrc + tid + 256);
        if (tid < 208) sm.t4[tid + 512] = __ldg(gsrc + tid + 512);
    }
    __syncthreads();

    int w = tid >> 5, l = tid & 31;
    int s = blockIdx.x * 8 + w;
    int line = s >> 6, q0 = (s & 63) << 2;

    ull base;
    {
        const char* gp = (const char*)g_accT + l * 16;
        asm("cvta.to.global.u64 %0, %1;" : "=l"(base) : "l"(gp));
    }

    // acc[4p+0..1] = half0 (ch 4l..4l+3), acc[4p+2..3] = half1 (ch 128+4l..)
    ull acc[16];
#pragma unroll
    for (int i = 0; i < 16; i++) acc[i] = 0ull;

    ull v0 = 0, v1 = 0, v2 = 0, v3 = 0;   // row r / r+2
    ull w0 = 0, w1 = 0, w2 = 0, w3 = 0;   // row r+1 / r+3 (predicated)

    for (int a = 0; a < 90; a++) {
        uint4 o = sm.t4[w * 90 + a];             // warp-uniform offsets px0..3
        unsigned lo = min(o.x, o.w), hi = max(o.x, o.w);   // monotone strip

        LDG2(v0, v1, base + lo);                 // row 0, always
        LDG2(v2, v3, base + lo + 512);
        unsigned off1 = lo + 1024;
        unsigned c1 = (hi >= off1);
        PLDG2B(w0, w1, c1, base + off1);         // row 1, if it exists
        PLDG2B(w2, w3, c1, base + off1 + 512);

        PADD4(acc[0],  acc[1],  acc[2],  acc[3],  v0, v1, v2, v3, o.x, lo);
        PADD4(acc[4],  acc[5],  acc[6],  acc[7],  v0, v1, v2, v3, o.y, lo);
        PADD4(acc[8],  acc[9],  acc[10], acc[11], v0, v1, v2, v3, o.z, lo);
        PADD4(acc[12], acc[13], acc[14], acc[15], v0, v1, v2, v3, o.w, lo);

        PADD4(acc[0],  acc[1],  acc[2],  acc[3],  w0, w1, w2, w3, o.x, off1);
        PADD4(acc[4],  acc[5],  acc[6],  acc[7],  w0, w1, w2, w3, o.y, off1);
        PADD4(acc[8],  acc[9],  acc[10], acc[11], w0, w1, w2, w3, o.z, off1);
        PADD4(acc[12], acc[13], acc[14], acc[15], w0, w1, w2, w3, o.w, off1);

        unsigned off2 = lo + 2048;
        if (hi >= off2) {                        // warp-uniform, ~29% taken
            LDG2(v0, v1, base + off2);
            LDG2(v2, v3, base + off2 + 512);
            unsigned off3 = lo + 3072;
            unsigned c3 = (hi >= off3);
            PLDG2B(w0, w1, c3, base + off3);
            PLDG2B(w2, w3, c3, base + off3 + 512);

            PADD4(acc[0],  acc[1],  acc[2],  acc[3],  v0, v1, v2, v3, o.x, off2);
            PADD4(acc[4],  acc[5],  acc[6],  acc[7],  v0, v1, v2, v3, o.y, off2);
            PADD4(acc[8],  acc[9],  acc[10], acc[11], v0, v1, v2, v3, o.z, off2);
            PADD4(acc[12], acc[13], acc[14], acc[15], v0, v1, v2, v3, o.w, off2);

            PADD4(acc[0],  acc[1],  acc[2],  acc[3],  w0, w1, w2, w3, o.x, off3);
            PADD4(acc[4],  acc[5],  acc[6],  acc[7],  w0, w1, w2, w3, o.y, off3);
            PADD4(acc[8],  acc[9],  acc[10], acc[11], w0, w1, w2, w3, o.z, off3);
            PADD4(acc[12], acc[13], acc[14], acc[15], w0, w1, w2, w3, o.w, off3);
        }
    }

    if (PASS == 1) {
        // pixel-major staging: pix = x*256 + y = line*256 + q0 + p
#pragma unroll
        for (int p = 0; p < 4; p++) {
            ull* pw = g_pBT + ((size_t)line * 256 + q0 + p) * 128;
            *reinterpret_cast<ulonglong2*>(pw + l * 2) =
                make_ulonglong2(acc[4 * p], acc[4 * p + 1]);
            *reinterpret_cast<ulonglong2*>(pw + 64 + l * 2) =
                make_ulonglong2(acc[4 * p + 2], acc[4 * p + 3]);
        }
        return;
    }

    // PASS A: fold pass-B partials; pixel (x=q0+p, y=line) -> pix = x*256+y
#pragma unroll
    for (int p = 0; p < 4; p++) {
        const ull* pr = g_pBT + ((size_t)(q0 + p) * 256 + line) * 128;
        ulonglong2 b0 = __ldg(reinterpret_cast<const ulonglong2*>(pr + l * 2));
        ulonglong2 b1 = __ldg(reinterpret_cast<const ulonglong2*>(pr + 64 + l * 2));
        acc[4 * p]     = fadd2(acc[4 * p],     b0.x);
        acc[4 * p + 1] = fadd2(acc[4 * p + 1], b0.y);
        acc[4 * p + 2] = fadd2(acc[4 * p + 2], b1.x);
        acc[4 * p + 3] = fadd2(acc[4 * p + 3], b1.y);
    }

    // epilogue: stage [32 px][256 ch] in SMEM, re-read channel-major,
    // store 32 contiguous x per channel (full-line coalesced)
    __syncthreads();   // table reads done before overwriting the union
#pragma unroll
    for (int p = 0; p < 4; p++) {
        float* st = sm.stage + (size_t)(w * 4 + p) * 264;
        *reinterpret_cast<float4*>(st + l * 4) =
            make_float4(u64lo(acc[4 * p]),     u64hi(acc[4 * p]),
                        u64lo(acc[4 * p + 1]), u64hi(acc[4 * p + 1]));
        *reinterpret_cast<float4*>(st + 128 + l * 4) =
            make_float4(u64lo(acc[4 * p + 2]), u64hi(acc[4 * p + 2]),
                        u64lo(acc[4 * p + 3]), u64hi(acc[4 * p + 3]));
    }
    __syncthreads();

    // thread tid == channel nc; CTA covers x in [X0, X0+32) at row `line`
    int X0 = (blockIdx.x & 7) << 5;
    float* op = outp + (size_t)tid * HW + (line << 8) + X0;
#pragma unroll
    for (int k = 0; k < 8; k++) {
        float4 q = make_float4(sm.stage[(size_t)(4 * k + 0) * 264 + tid],
                               sm.stage[(size_t)(4 * k + 1) * 264 + tid],
                               sm.stage[(size_t)(4 * k + 2) * 264 + tid],
                               sm.stage[(size_t)(4 * k + 3) * 264 + tid]);
        *reinterpret_cast<float4*>(op + 4 * k) = q;
    }
}

extern "C" void kernel_launch(void* const* d_in, const int* in_sizes, int n_in,
                              void* d_out, int out_size) {
    const float* acc = (const float*)d_in[0];
    float* out = (float*)d_out;

    k_trig<<<1, 192>>>();
    k_transpose<<<dim3(AR / 32, NC / 32), dim3(32, 8)>>>(acc);
    k_tab<<<NA * HW / 256, 256>>>();          // 46080 blocks
    k_pass<1><<<2048, 256>>>(out);            // pass B -> g_pBT (pixel-major)
    k_pass<0><<<2048, 256>>>(out);            // pass A: += pBT fold, -> out
}

// round 10
// speedup vs baseline: 1.7319x; 1.7319x over previous
#include <cuda_runtime.h>

// Inverse discrete Hough transform, round 10: pattern-sorted group gather.
// Per (4-px strip, angle) the rho rows form one of 15 monotone patterns
// (3 boundary bits + sign). The table builder SORTS each strip's 90 angles
// by pattern; the main kernel runs 15 straight-line loops: per angle only
// the k<=4 DISTINCT rows are loaded (independent LDG.128) and exactly 16
// packed f32x2 adds route them to pixels with compile-time indices.
// -> minimal loads (R5-level traffic) + zero predication (unlike R9) +
//    zero load chains (unlike R3-R7).
// Pass B: angles 0..44 & 135..179, strips along y -> pBT[x*256+y][nc]
// Pass A: angles 45..134, strips along x, += pBT fold, -> out.

#define NA 180
#define NR 400
#define NC 256
#define OH 256
#define OW 256
#define AR (NA * NR)      // 72000
#define HW (OH * OW)      // 65536
#define NS4 16384         // strips of 4 px per pass
#define TS 96             // u32 per strip table: 4 (cum counts) + 90 offs + pad

typedef unsigned long long ull;

__device__ float  g_accT[AR * NC];                 // 73.7 MB: [a*400+r][nc]
__device__ float2 g_trig[NA];
__device__ unsigned g_tabA[(size_t)NS4 * TS];      // sorted per-strip tables
__device__ unsigned g_tabB[(size_t)NS4 * TS];
__device__ ull    g_pBT[(size_t)HW * 128];         // pass-B partial [x*256+y][nc/2]

__device__ __forceinline__ ull fadd2(ull a, ull b) {
    ull r;
    asm("add.rn.f32x2 %0, %1, %2;" : "=l"(r) : "l"(a), "l"(b));
    return r;
}
__device__ __forceinline__ float u64lo(ull u) {
    float a, b; asm("mov.b64 {%0,%1}, %2;" : "=f"(a), "=f"(b) : "l"(u)); return a;
}
__device__ __forceinline__ float u64hi(ull u) {
    float a, b; asm("mov.b64 {%0,%1}, %2;" : "=f"(a), "=f"(b) : "l"(u)); return b;
}
#define LDG2(v0, v1, addr)                                             \
    asm("ld.global.nc.v2.u64 {%0,%1}, [%2];"                           \
        : "=l"(v0), "=l"(v1) : "l"(addr))

__global__ void k_trig() {
    int a = threadIdx.x;
    if (a < NA) {
        // f32 theta (rn multiply), then correctly-rounded f32 cos/sin via
        // double (immune to fast-math; matches the JAX reference bit-exactly).
        float t = __fmul_rn((float)a, (float)(3.14159265358979323846 / 180.0));
        double td = (double)t;
        g_trig[a] = make_float2((float)cos(td), (float)sin(td));
    }
}

// 32x32 tiled transpose of acc[256][72000] -> g_accT[72000][256]
__global__ void k_transpose(const float* __restrict__ in) {
    __shared__ float tile[32][33];
    int tx = threadIdx.x, ty = threadIdx.y;           // 32 x 8
    int ar = blockIdx.x * 32 + tx;
#pragma unroll
    for (int k = 0; k < 4; k++)
        tile[ty + k * 8][tx] = in[(size_t)(blockIdx.y * 32 + ty + k * 8) * AR + ar];
    __syncthreads();
    int nc2 = blockIdx.y * 32 + tx;
#pragma unroll
    for (int k = 0; k < 4; k++)
        g_accT[(size_t)(blockIdx.x * 32 + ty + k * 8) * NC + nc2] = tile[tx][ty + k * 8];
}

// Table builder: one warp per strip. Computes exact offsets, classifies the
// pattern code (0 = flat; 1..7 ascending bits; 9..15 descending), and writes
// the 90 base offsets sorted by code plus 16 cumulative u8 counts.
template <int PASS>
__global__ void k_tab() {
    int tid = threadIdx.x, w = tid >> 5, l = tid & 31;
    int s = blockIdx.x * 8 + w;
    unsigned* tabw = ((PASS == 0) ? g_tabA : g_tabB) + (size_t)s * TS;
    int line = s >> 6, q0 = (s & 63) << 2;

    unsigned codev[3], basev[3];
#pragma unroll
    for (int i = 0; i < 3; i++) {
        int ar = i * 32 + l;
        codev[i] = 0xFFFFu;
        if (ar < 90) {
            int a = (PASS == 0) ? (45 + ar) : (ar < 45 ? ar : ar + 90);
            float2 cs = g_trig[a];
            unsigned off[4];
#pragma unroll
            for (int p = 0; p < 4; p++) {
                int x = (PASS == 0) ? (q0 + p) : line;
                int y = (PASS == 0) ? line : (q0 + p);
                // exact reference arithmetic: rn(rn(xc*c)+rn(yc*s)), rne round
                float sum = __fadd_rn(__fmul_rn((float)(x - 128), cs.x),
                                      __fmul_rn((float)(y - 128), cs.y));
                off[p] = (unsigned)(a * NR + __float2int_rn(sum) + 200) << 10;
            }
            int d1 = ((int)(off[1] - off[0])) >> 10;
            int d2 = ((int)(off[2] - off[0])) >> 10;
            int d3 = ((int)(off[3] - off[0])) >> 10;
            int b1 = d1 != 0, b2 = d2 != d1, b3 = d3 != d2;
            int bits = b1 | (b2 << 1) | (b3 << 2);
            int neg = (d1 < 0) | (d2 < 0) | (d3 < 0);
            codev[i] = (bits == 0) ? 0u : (unsigned)(bits + (neg ? 8 : 0));
            basev[i] = off[0];
        }
    }

    unsigned lmlt = (1u << l) - 1u;
    int cnt = 0;
    unsigned cword[4] = {0, 0, 0, 0};
#pragma unroll
    for (int c = 0; c < 16; c++) {
#pragma unroll
        for (int i = 0; i < 3; i++) {
            bool v = (codev[i] == (unsigned)c);
            unsigned m = __ballot_sync(0xFFFFFFFFu, v);
            if (v) tabw[4 + cnt + __popc(m & lmlt)] = basev[i];
            cnt += __popc(m);
        }
        cword[c >> 2] |= (unsigned)cnt << ((c & 3) * 8);
    }
    if (l == 0) {
        tabw[0] = cword[0]; tabw[1] = cword[1];
        tabw[2] = cword[2]; tabw[3] = cword[3];
    }
}

// One pattern group: n angles, K distinct rows at off + S*1024*{0..K-1};
// pixel p uses row {0, P1, P2, P3}[p]. Straight-line, no predication.
template <int K, int S, int P1, int P2, int P3>
__device__ __forceinline__ void run_group(int n, const unsigned* toff,
                                          int& idx, ull base, ull* acc) {
    for (int i = 0; i < n; i++) {
        ull addr = base + toff[idx + i];
        ull r[K][4];
#pragma unroll
        for (int j = 0; j < K; j++) {
            LDG2(r[j][0], r[j][1], addr + S * 1024 * j);
            LDG2(r[j][2], r[j][3], addr + S * 1024 * j + 512);
        }
#pragma unroll
        for (int q = 0; q < 4; q++) acc[q]      = fadd2(acc[q],      r[0][q]);
#pragma unroll
        for (int q = 0; q < 4; q++) acc[4 + q]  = fadd2(acc[4 + q],  r[P1][q]);
#pragma unroll
        for (int q = 0; q < 4; q++) acc[8 + q]  = fadd2(acc[8 + q],  r[P2][q]);
#pragma unroll
        for (int q = 0; q < 4; q++) acc[12 + q] = fadd2(acc[12 + q], r[P3][q]);
    }
    idx += n;
}

// Main pass. CTA = 8 warps = 8 consecutive 4-px strips; warp = strip x 256 ch
// (lane = 16B channel slice, two 128-ch halves). Sorted table in SMEM.
template <int PASS>
__global__ __launch_bounds__(256, 3) void k_pass(float* __restrict__ outp) {
    __shared__ union SM {
        unsigned tw[8 * TS];         // 8 strip tables (3 KB)
        float stage[32 * 264];       // pass-A epilogue: 32 px x 256 ch (pad 8)
    } sm;

    const unsigned* tab = (PASS == 0) ? g_tabA : g_tabB;
    int tid = threadIdx.x;
    if (tid < 192)
        ((uint4*)sm.tw)[tid] =
            __ldg((const uint4*)(tab + (size_t)blockIdx.x * 8 * TS) + tid);
    __syncthreads();

    int w = tid >> 5, l = tid & 31;
    int s = blockIdx.x * 8 + w;
    int line = s >> 6, q0 = (s & 63) << 2;

    const unsigned* tw = sm.tw + w * TS;
    const unsigned char* cb = (const unsigned char*)tw;   // 16 cumulative counts
    const unsigned* toff = tw + 4;

    ull base;
    {
        const char* gp = (const char*)g_accT + l * 16;
        asm("cvta.to.global.u64 %0, %1;" : "=l"(base) : "l"(gp));
    }

    // acc[4p+0..1] = half0 (ch 4l..), acc[4p+2..3] = half1 (ch 128+4l..)
    ull acc[16];
#pragma unroll
    for (int i = 0; i < 16; i++) acc[i] = 0ull;

    int idx = 0;
#define GC(c) ((int)cb[c] - ((c) ? (int)cb[(c)-1] : 0))
    run_group<1,  1, 0, 0, 0>(GC(0),  toff, idx, base, acc);
    run_group<2,  1, 1, 1, 1>(GC(1),  toff, idx, base, acc);
    run_group<2,  1, 0, 1, 1>(GC(2),  toff, idx, base, acc);
    run_group<3,  1, 1, 2, 2>(GC(3),  toff, idx, base, acc);
    run_group<2,  1, 0, 0, 1>(GC(4),  toff, idx, base, acc);
    run_group<3,  1, 1, 1, 2>(GC(5),  toff, idx, base, acc);
    run_group<3,  1, 0, 1, 2>(GC(6),  toff, idx, base, acc);
    run_group<4,  1, 1, 2, 3>(GC(7),  toff, idx, base, acc);
    // code 8 impossible (flat+neg); cumulative counts skip it
    run_group<2, -1, 1, 1, 1>(GC(9),  toff, idx, base, acc);
    run_group<2, -1, 0, 1, 1>(GC(10), toff, idx, base, acc);
    run_group<3, -1, 1, 2, 2>(GC(11), toff, idx, base, acc);
    run_group<2, -1, 0, 0, 1>(GC(12), toff, idx, base, acc);
    run_group<3, -1, 1, 1, 2>(GC(13), toff, idx, base, acc);
    run_group<3, -1, 0, 1, 2>(GC(14), toff, idx, base, acc);
    run_group<4, -1, 1, 2, 3>(GC(15), toff, idx, base, acc);
#undef GC

    if (PASS == 1) {
        // pixel-major staging: pix = x*256 + y = line*256 + q0 + p
#pragma unroll
        for (int p = 0; p < 4; p++) {
            ull* pw = g_pBT + ((size_t)line * 256 + q0 + p) * 128;
            *reinterpret_cast<ulonglong2*>(pw + l * 2) =
                make_ulonglong2(acc[4 * p], acc[4 * p + 1]);
            *reinterpret_cast<ulonglong2*>(pw + 64 + l * 2) =
                make_ulonglong2(acc[4 * p + 2], acc[4 * p + 3]);
        }
        return;
    }

    // PASS A: fold pass-B partials; pixel (x=q0+p, y=line) -> pix = x*256+y
#pragma unroll
    for (int p = 0; p < 4; p++) {
        const ull* pr = g_pBT + ((size_t)(q0 + p) * 256 + line) * 128;
        ulonglong2 b0 = __ldg(reinterpret_cast<const ulonglong2*>(pr + l * 2));
        ulonglong2 b1 = __ldg(reinterpret_cast<const ulonglong2*>(pr + 64 + l * 2));
        acc[4 * p]     = fadd2(acc[4 * p],     b0.x);
        acc[4 * p + 1] = fadd2(acc[4 * p + 1], b0.y);
        acc[4 * p + 2] = fadd2(acc[4 * p + 2], b1.x);
        acc[4 * p + 3] = fadd2(acc[4 * p + 3], b1.y);
    }

    // epilogue: stage [32 px][256 ch] in SMEM, re-read channel-major,
    // store 32 contiguous x per channel (full-line coalesced)
    __syncthreads();   // table reads done before overwriting the union
#pragma unroll
    for (int p = 0; p < 4; p++) {
        float* st = sm.stage + (size_t)(w * 4 + p) * 264;
        *reinterpret_cast<float4*>(st + l * 4) =
            make_float4(u64lo(acc[4 * p]),     u64hi(acc[4 * p]),
                        u64lo(acc[4 * p + 1]), u64hi(acc[4 * p + 1]));
        *reinterpret_cast<float4*>(st + 128 + l * 4) =
            make_float4(u64lo(acc[4 * p + 2]), u64hi(acc[4 * p + 2]),
                        u64lo(acc[4 * p + 3]), u64hi(acc[4 * p + 3]));
    }
    __syncthreads();

    // thread tid == channel nc; CTA covers x in [X0, X0+32) at row `line`
    int X0 = (blockIdx.x & 7) << 5;
    float* op = outp + (size_t)tid * HW + (line << 8) + X0;
#pragma unroll
    for (int k = 0; k < 8; k++) {
        float4 q = make_float4(sm.stage[(size_t)(4 * k + 0) * 264 + tid],
                               sm.stage[(size_t)(4 * k + 1) * 264 + tid],
                               sm.stage[(size_t)(4 * k + 2) * 264 + tid],
                               sm.stage[(size_t)(4 * k + 3) * 264 + tid]);
        *reinterpret_cast<float4*>(op + 4 * k) = q;
    }
}

extern "C" void kernel_launch(void* const* d_in, const int* in_sizes, int n_in,
                              void* d_out, int out_size) {
    const float* acc = (const float*)d_in[0];
    float* out = (float*)d_out;

    k_trig<<<1, 192>>>();
    k_transpose<<<dim3(AR / 32, NC / 32), dim3(32, 8)>>>(acc);
    k_tab<0><<<NS4 / 8, 256>>>();             // sorted table, pass A
    k_tab<1><<<NS4 / 8, 256>>>();             // sorted table, pass B
    k_pass<1><<<NS4 / 8, 256>>>(out);         // pass B -> g_pBT (pixel-major)
    k_pass<0><<<NS4 / 8, 256>>>(out);         // pass A: += pBT fold, -> out
}